// round 16
// baseline (speedup 1.0000x reference)
#include <cuda_runtime.h>
#include <cuda_bf16.h>
#include <cstddef>

// LengthRegulator, single fused kernel (R16): single-wave multi-tile blocks.
//   Grid = (32, 16) = 512 blocks x 512 threads; with regs~32 this is 4
//   blocks/SM x 148 SMs = 592 slots -> ONE wave, zero wave transitions.
//   Each block: one warp-shuffle scan of durations[b], one search of its 128
//   consecutive frames, then 4 copy tiles of 32 frames (no barriers between
//   tiles). Copy per tile identical to the proven R12 shape: thread owns
//   column e of 8 consecutive frames, 8 independent LDG.128 then 8 __stcs.
// B=16, S=512, H=512 fixed; T derived from out_size.

#define LR_B    16
#define LR_S    512
#define LR_V    128       // float4 per row (H=512)
#define LR_FPB  128       // frames per block (4 tiles of 32)
#define LR_THR  512
#define LR_CHNK 32        // blocks per batch (T / LR_FPB)

__global__ __launch_bounds__(LR_THR)
void lr_fused_kernel(const float4* __restrict__ x4,
                     const int*    __restrict__ dur,
                     float4*       __restrict__ out4,
                     int T)
{
    __shared__ int cum[LR_S];
    __shared__ int sh_w[16];
    __shared__ int sidx[LR_FPB];

    const int b    = blockIdx.y;
    const int f0   = blockIdx.x * LR_FPB;
    const int tid  = threadIdx.x;
    const int wid  = tid >> 5;       // 0..15
    const int lane = tid & 31;

    // ---- warp-shuffle inclusive scan of durations[b, :] (1 elem/thread) ----
    int v = dur[b * LR_S + tid];
#pragma unroll
    for (int off = 1; off < 32; off <<= 1) {
        int n = __shfl_up_sync(0xFFFFFFFFu, v, off);
        if (lane >= off) v += n;
    }
    if (lane == 31) sh_w[wid] = v;
    __syncthreads();
    if (wid == 0 && lane < 16) {
        int w  = sh_w[lane];
        int vv = w;
#pragma unroll
        for (int off = 1; off < 16; off <<= 1) {
            int n = __shfl_up_sync(0xFFFFu, vv, off);
            if (lane >= off) vv += n;
        }
        sh_w[lane] = vv - w;          // exclusive warp offset
    }
    __syncthreads();
    cum[tid] = v + sh_w[wid];         // inclusive cumsum
    __syncthreads();

    // ---- searchsorted(right) for this block's 128 frames ----
    if (tid < LR_FPB) {
        int t = f0 + tid;
        int lo = 0, hi = LR_S;
        while (lo < hi) {
            int mid = (lo + hi) >> 1;
            if (cum[mid] <= t) lo = mid + 1; else hi = mid;
        }
        sidx[tid] = (lo < LR_S) ? (b * LR_S + lo) : -1;
    }
    __syncthreads();

    // ---- copy: 4 tiles of 32 frames; thread = column e of 8 consecutive
    //      frames per tile. No barriers between tiles. ----
    const int g = tid >> 7;           // 0..3
    const int e = tid & 127;          // vec4 column within row

    float4* base = out4 + ((size_t)b * T + f0) * LR_V;

#pragma unroll
    for (int t = 0; t < 4; t++) {
        const int fbase = t * 32 + g * 8;   // local frame of this 8-group

        float4 val[8];
#pragma unroll
        for (int j = 0; j < 8; j++) {
            int row = sidx[fbase + j];
            val[j] = make_float4(0.f, 0.f, 0.f, 0.f);
            if (row >= 0)
                val[j] = __ldg(&x4[(size_t)row * LR_V + e]);
        }
#pragma unroll
        for (int j = 0; j < 8; j++)
            __stcs(&base[(size_t)(fbase + j) * LR_V + e], val[j]);
    }
}

// ---------------- generic fallback (any shape; unused here) ----------------
__global__ void lr_generic_kernel(const float* __restrict__ x,
                                  const int* __restrict__ dur,
                                  float* __restrict__ out,
                                  int B, int S, int H, int T)
{
    size_t i = (size_t)blockIdx.x * blockDim.x + threadIdx.x;
    size_t total = (size_t)B * T * H;
    if (i >= total) return;
    int e = (int)(i % H);
    int t = (int)((i / H) % T);
    int b = (int)(i / ((size_t)T * H));
    int c = 0, idx = S;
    for (int j = 0; j < S; j++) { c += dur[b * S + j]; if (c > t) { idx = j; break; } }
    out[i] = (idx < S) ? x[((size_t)b * S + idx) * H + e] : 0.f;
}

extern "C" void kernel_launch(void* const* d_in, const int* in_sizes, int n_in,
                              void* d_out, int out_size)
{
    const float* x   = (const float*)d_in[0];
    const int*   dur = (const int*)d_in[1];
    float*       out = (float*)d_out;

    const int BS = in_sizes[1];              // B * S = 8192
    const int H  = in_sizes[0] / BS;         // 512
    const int T  = out_size / (LR_B * H);    // 4096
    const int S  = BS / LR_B;

    if (H == 512 && S == LR_S && (T % LR_FPB) == 0) {
        dim3 grid(T / LR_FPB, LR_B);         // (32, 16) = 512 blocks
        lr_fused_kernel<<<grid, LR_THR>>>((const float4*)x, dur,
                                          (float4*)out, T);
    } else {
        size_t total = (size_t)out_size;
        int blocks = (int)((total + 255) / 256);
        lr_generic_kernel<<<blocks, 256>>>(x, dur, out, LR_B, S, H, T);
    }
}